// round 14
// baseline (speedup 1.0000x reference)
#include <cuda_runtime.h>
#include <math.h>
#include <stdint.h>

#define D    128
#define D4   512
#define MAXN 100000
#define MAXE 1000000

// ---------------- scratch (no allocations allowed) ----------------
__device__ float g_H  [MAXN * D];    // gelu(LN1(x)) / LN2(conv), tf32-rounded
__device__ float g_HW [MAXN * D];    // h @ W_conv (raw fp32)
__device__ float g_F1 [MAXN * D4];   // FFN hidden, tf32-rounded
__device__ float g_Wr [D * D + 2 * D * D4];  // tf32-rounded Wc | W1 | W2
__device__ int   g_deg [MAXN];
__device__ int   g_scanI[MAXN];
__device__ int   g_bsum[128];
__device__ int   g_off [MAXN + 1];
__device__ int   g_pos [MAXN];
__device__ int   g_csr [MAXE];
__device__ float g_dinv[MAXN];
__device__ int   g_eflag;            // 1 => edge_index stored as int32

#define WR_WC 0
#define WR_W1 (D * D)
#define WR_W2 (D * D + D * D4)

__device__ __forceinline__ float gelu_f(float x) {
    return 0.5f * x * (1.0f + erff(x * 0.70710678118654752f));
}
__device__ __forceinline__ float tf32r(float x) {   // round to tf32 grid
    uint32_t r;
    asm("cvt.rna.tf32.f32 %0, %1;" : "=r"(r) : "f"(x));
    return __uint_as_float(r);
}
__device__ __forceinline__ uint32_t smem_u32(const void* p) {
    uint32_t a;
    asm("{ .reg .u64 t; cvta.to.shared.u64 t, %1; cvt.u32.u64 %0, t; }"
        : "=r"(a) : "l"(p));
    return a;
}
#define MMA_TF32(acc, a, b) \
    asm volatile( \
        "mma.sync.aligned.m16n8k8.row.col.f32.tf32.tf32.f32 " \
        "{%0,%1,%2,%3}, {%4,%5,%6,%7}, {%8,%9}, {%0,%1,%2,%3};" \
        : "+f"((acc)[0]), "+f"((acc)[1]), "+f"((acc)[2]), "+f"((acc)[3]) \
        : "r"((a)[0]), "r"((a)[1]), "r"((a)[2]), "r"((a)[3]), \
          "r"((b)[0]), "r"((b)[1]))

// ------- detect edge dtype + zero degree (side stream) -------
__global__ void k_detect_init(const unsigned long long* __restrict__ p, long long E,
                              unsigned long long NN, int N) {
    int i = blockIdx.x * blockDim.x + threadIdx.x;
    if (i < N) g_deg[i] = 0;
    if (blockIdx.x == 0) {
        __shared__ int bad;
        if (threadIdx.x == 0) bad = 0;
        __syncthreads();
        long long step = E / (long long)blockDim.x;
        if (step < 1) step = 1;
        long long idx = (long long)threadIdx.x * step;
        if (idx < E && p[idx] >= NN) bad = 1;
        __syncthreads();
        if (threadIdx.x == 0) g_eflag = bad;
    }
}

// ------- round Wc (main stream, before GEMM1) -------
__global__ void k_prepwc(const float* __restrict__ Wc) {
    int i = blockIdx.x * blockDim.x + threadIdx.x;
    if (i < D * D) g_Wr[WR_WC + i] = tf32r(Wc[i]);
}

// ------- round W1,W2 (side stream) -------
__global__ void k_prepw12(const float* __restrict__ W1, const float* __restrict__ W2) {
    int i = blockIdx.x * blockDim.x + threadIdx.x;
    if (i < D * D4) {
        g_Wr[WR_W1 + i] = tf32r(W1[i]);
        g_Wr[WR_W2 + i] = tf32r(W2[i]);
    }
}

// ---------------- LN1 + gelu (tf32-rounded output) ----------------
__global__ void k_rowln1(const float* __restrict__ x,
                         const float* __restrict__ g, const float* __restrict__ b,
                         float* __restrict__ out, int N) {
    int row = blockIdx.x * blockDim.y + threadIdx.y;
    if (row >= N) return;
    int l = threadIdx.x;
    float4 v = ((const float4*)(x + (size_t)row * D))[l];
    float s  = v.x + v.y + v.z + v.w;
    float ss = v.x*v.x + v.y*v.y + v.z*v.z + v.w*v.w;
    #pragma unroll
    for (int o = 16; o; o >>= 1) {
        s  += __shfl_xor_sync(0xffffffffu, s,  o);
        ss += __shfl_xor_sync(0xffffffffu, ss, o);
    }
    float mu  = s * (1.0f / D);
    float var = ss * (1.0f / D) - mu * mu;
    float rs  = rsqrtf(var + 1e-5f);
    float4 gg = ((const float4*)g)[l];
    float4 bb = ((const float4*)b)[l];
    float4 r;
    r.x = tf32r(gelu_f((v.x - mu) * rs * gg.x + bb.x));
    r.y = tf32r(gelu_f((v.y - mu) * rs * gg.y + bb.y));
    r.z = tf32r(gelu_f((v.z - mu) * rs * gg.z + bb.z));
    r.w = tf32r(gelu_f((v.w - mu) * rs * gg.w + bb.w));
    ((float4*)(out + (size_t)row * D))[l] = r;
}

// ---------------- degree histogram ----------------
__global__ void k_degcount(const void* __restrict__ ei, int E) {
    int e = blockIdx.x * blockDim.x + threadIdx.x;
    if (e >= E) return;
    int dst;
    if (g_eflag) dst = ((const int*)ei)[E + e];
    else         dst = (int)((const long long*)ei)[E + e];
    atomicAdd(&g_deg[dst], 1);
}

// ---------------- parallel 3-phase scan ----------------
__global__ void k_scan1(int N) {
    __shared__ int sm[1024];
    int i = blockIdx.x * 1024 + threadIdx.x;
    int v = (i < N) ? g_deg[i] : 0;
    sm[threadIdx.x] = v;
    __syncthreads();
    #pragma unroll
    for (int off = 1; off < 1024; off <<= 1) {
        int t = (threadIdx.x >= off) ? sm[threadIdx.x - off] : 0;
        __syncthreads();
        sm[threadIdx.x] += t;
        __syncthreads();
    }
    if (i < N) g_scanI[i] = sm[threadIdx.x];
    if (threadIdx.x == 1023) g_bsum[blockIdx.x] = sm[1023];
}
__global__ void k_scan2(int NB) {
    __shared__ int sm[128];
    int t = threadIdx.x;
    sm[t] = (t < NB) ? g_bsum[t] : 0;
    __syncthreads();
    #pragma unroll
    for (int off = 1; off < 128; off <<= 1) {
        int v = (t >= off) ? sm[t - off] : 0;
        __syncthreads();
        sm[t] += v;
        __syncthreads();
    }
    if (t < NB) g_bsum[t] = sm[t];
}
__global__ void k_scan3(int N, int E) {
    int i = blockIdx.x * blockDim.x + threadIdx.x;
    if (i > N) return;
    if (i == N) { g_off[N] = E; return; }
    int blk = i >> 10;
    int base = blk ? g_bsum[blk - 1] : 0;
    int d = g_deg[i];
    int off = base + g_scanI[i] - d;
    g_off[i] = off;
    g_pos[i] = off;
    g_dinv[i] = rsqrtf((float)(d + 1));
}

// ---------------- CSR fill ----------------
__global__ void k_fill(const void* __restrict__ ei, int E) {
    int e = blockIdx.x * blockDim.x + threadIdx.x;
    if (e >= E) return;
    int s, d2;
    if (g_eflag) { const int* p = (const int*)ei; s = p[e]; d2 = p[E + e]; }
    else { const long long* p = (const long long*)ei; s = (int)p[e]; d2 = (int)p[E + e]; }
    int pos = atomicAdd(&g_pos[d2], 1);
    g_csr[pos] = s;
}

// ------- gather (MLP=4) fused with LN2 (tf32-rounded output) -------
__global__ void k_gather_ln2(const float* __restrict__ x,
                             const float* __restrict__ bconv,
                             const float* __restrict__ g, const float* __restrict__ b,
                             float* __restrict__ out, int N) {
    int row = blockIdx.x * (blockDim.x >> 5) + (threadIdx.x >> 5);
    if (row >= N) return;
    int lane = threadIdx.x & 31;
    float di = g_dinv[row];
    float4 acc = ((const float4*)g_HW)[row * 32 + lane];   // self term
    acc.x *= di; acc.y *= di; acc.z *= di; acc.w *= di;
    int e = g_off[row], e1 = g_off[row + 1];
    for (; e + 4 <= e1; e += 4) {
        int s0 = g_csr[e], s1 = g_csr[e + 1], s2 = g_csr[e + 2], s3 = g_csr[e + 3];
        float c0 = g_dinv[s0], c1 = g_dinv[s1], c2 = g_dinv[s2], c3 = g_dinv[s3];
        float4 v0 = ((const float4*)g_HW)[s0 * 32 + lane];
        float4 v1 = ((const float4*)g_HW)[s1 * 32 + lane];
        float4 v2 = ((const float4*)g_HW)[s2 * 32 + lane];
        float4 v3 = ((const float4*)g_HW)[s3 * 32 + lane];
        acc.x += (v0.x*c0 + v1.x*c1) + (v2.x*c2 + v3.x*c3);
        acc.y += (v0.y*c0 + v1.y*c1) + (v2.y*c2 + v3.y*c3);
        acc.z += (v0.z*c0 + v1.z*c1) + (v2.z*c2 + v3.z*c3);
        acc.w += (v0.w*c0 + v1.w*c1) + (v2.w*c2 + v3.w*c3);
    }
    for (; e < e1; e++) {
        int s = g_csr[e];
        float c = g_dinv[s];
        float4 v = ((const float4*)g_HW)[s * 32 + lane];
        acc.x += v.x*c; acc.y += v.y*c; acc.z += v.z*c; acc.w += v.w*c;
    }
    float4 xv  = ((const float4*)x)[row * 32 + lane];
    float4 bcv = ((const float4*)bconv)[lane];
    float4 v;
    v.x = xv.x + acc.x * di + bcv.x;
    v.y = xv.y + acc.y * di + bcv.y;
    v.z = xv.z + acc.z * di + bcv.z;
    v.w = xv.w + acc.w * di + bcv.w;
    float s  = v.x + v.y + v.z + v.w;
    float ss = v.x*v.x + v.y*v.y + v.z*v.z + v.w*v.w;
    #pragma unroll
    for (int o = 16; o; o >>= 1) {
        s  += __shfl_xor_sync(0xffffffffu, s,  o);
        ss += __shfl_xor_sync(0xffffffffu, ss, o);
    }
    float mu  = s * (1.0f / D);
    float var = ss * (1.0f / D) - mu * mu;
    float rs  = rsqrtf(var + 1e-5f);
    float4 gg = ((const float4*)g)[lane];
    float4 bb = ((const float4*)b)[lane];
    float4 r;
    r.x = tf32r((v.x - mu) * rs * gg.x + bb.x);
    r.y = tf32r((v.y - mu) * rs * gg.y + bb.y);
    r.z = tf32r((v.z - mu) * rs * gg.z + bb.z);
    r.w = tf32r((v.w - mu) * rs * gg.w + bb.w);
    ((float4*)(out + (size_t)row * D))[lane] = r;
}

// ---- hi-occupancy tf32 GEMM: CTA tile 128x64, 3 CTA/SM ----
// warps 4(m)x2(n), warp tile 32x32. mode 0: raw. 1: tf32r(gelu(acc+bias)).
#define KCH 32
#define APITCH 36
#define WPITCH2 72
#define ABUF2 (128 * APITCH)
#define WBUF2 (KCH * WPITCH2)
#define GEMMH_SMEM ((2 * (ABUF2 + WBUF2)) * (int)sizeof(float))

__global__ void __launch_bounds__(256, 3) k_gemm_hi(
    const float* __restrict__ A, const float* __restrict__ W,
    const float* __restrict__ bias,
    float* __restrict__ out, int N, int K, int ncols, int mode)
{
    extern __shared__ float sm[];
    uint32_t smb = smem_u32(sm);
    int tid = threadIdx.x, wid = tid >> 5, lane = tid & 31;
    int rowBase = blockIdx.x * 128, colBase = blockIdx.y * 64;
    int wm = (wid & 3) * 32;
    int wn = (wid >> 2) * 32;
    int lq = lane >> 2, lr = lane & 3;

    auto issue = [&](int ch) {
        int kc = ch * KCH;
        int buf = ch & 1;
        uint32_t asb = smb + (uint32_t)(buf * ABUF2) * 4u;
        uint32_t wsb = smb + (uint32_t)(2 * ABUF2 + buf * WBUF2) * 4u;
        #pragma unroll
        for (int i = 0; i < 4; i++) {
            int c = tid + i * 256;            // A: 1024 chunks of 16B
            int r = c >> 3, kp = (c & 7) << 2;
            int gr = rowBase + r;
            const float* src = &A[(size_t)gr * K + kc + kp];
            uint32_t dst = asb + (uint32_t)(r * APITCH + kp) * 4u;
            int sz = (gr < N) ? 16 : 0;
            asm volatile("cp.async.ca.shared.global [%0], [%1], 16, %2;"
                         :: "r"(dst), "l"(src), "r"(sz));
        }
        #pragma unroll
        for (int i = 0; i < 2; i++) {
            int c = tid + i * 256;            // W: 512 chunks of 16B (32 x 64)
            int rr = c >> 4, np = (c & 15) << 2;
            const float* src = &W[(size_t)(kc + rr) * ncols + colBase + np];
            uint32_t dst = wsb + (uint32_t)(rr * WPITCH2 + np) * 4u;
            asm volatile("cp.async.ca.shared.global [%0], [%1], 16;"
                         :: "r"(dst), "l"(src));
        }
        asm volatile("cp.async.commit_group;");
    };

    float acc[2][4][4];
    #pragma unroll
    for (int i = 0; i < 2; i++)
        #pragma unroll
        for (int j = 0; j < 4; j++)
            #pragma unroll
            for (int k = 0; k < 4; k++) acc[i][j][k] = 0.0f;

    int nch = K / KCH;
    issue(0);
    for (int ch = 0; ch < nch; ch++) {
        if (ch + 1 < nch) {
            issue(ch + 1);
            asm volatile("cp.async.wait_group 1;");
        } else {
            asm volatile("cp.async.wait_group 0;");
        }
        __syncthreads();
        const float* As = sm + (ch & 1) * ABUF2;
        const float* Ws = sm + 2 * ABUF2 + (ch & 1) * WBUF2;
        #pragma unroll
        for (int ks = 0; ks < KCH; ks += 8) {
            uint32_t a[2][4], b[4][2];
            #pragma unroll
            for (int mf = 0; mf < 2; mf++) {
                int r0 = wm + mf * 16 + lq;
                a[mf][0] = __float_as_uint(As[r0 * APITCH + ks + lr]);
                a[mf][1] = __float_as_uint(As[(r0 + 8) * APITCH + ks + lr]);
                a[mf][2] = __float_as_uint(As[r0 * APITCH + ks + lr + 4]);
                a[mf][3] = __float_as_uint(As[(r0 + 8) * APITCH + ks + lr + 4]);
            }
            #pragma unroll
            for (int nf = 0; nf < 4; nf++) {
                int c0 = wn + nf * 8 + lq;
                b[nf][0] = __float_as_uint(Ws[(ks + lr) * WPITCH2 + c0]);
                b[nf][1] = __float_as_uint(Ws[(ks + lr + 4) * WPITCH2 + c0]);
            }
            #pragma unroll
            for (int mf = 0; mf < 2; mf++)
                #pragma unroll
                for (int nf = 0; nf < 4; nf++)
                    MMA_TF32(acc[mf][nf], a[mf], b[nf]);
        }
        __syncthreads();
    }

    #pragma unroll
    for (int mf = 0; mf < 2; mf++) {
        int r0 = rowBase + wm + mf * 16 + lq;
        #pragma unroll
        for (int half = 0; half < 2; half++) {
            int row = r0 + half * 8;
            if (row >= N) continue;
            #pragma unroll
            for (int nf = 0; nf < 4; nf++) {
                int col = colBase + wn + nf * 8 + lr * 2;
                float v0 = acc[mf][nf][half * 2];
                float v1 = acc[mf][nf][half * 2 + 1];
                if (mode == 1) {
                    v0 = tf32r(gelu_f(v0 + bias[col]));
                    v1 = tf32r(gelu_f(v1 + bias[col + 1]));
                }
                *(float2*)&out[(size_t)row * ncols + col] = make_float2(v0, v1);
            }
        }
    }
}

// ---- wide tf32 GEMM (R10): CTA tile 128x128, 2 CTA/SM. For GEMM3 only ----
// mode 2: res + gelu(acc+bias).
#define WPITCH 136
#define ABUF (128 * APITCH)
#define WBUF (KCH * WPITCH)
#define GEMM_SMEM ((2 * (ABUF + WBUF)) * (int)sizeof(float))

__global__ void __launch_bounds__(256, 2) k_gemm_tc(
    const float* __restrict__ A, const float* __restrict__ W,
    const float* __restrict__ bias, const float* __restrict__ res,
    float* __restrict__ out, int N, int K, int ncols)
{
    extern __shared__ float sm[];
    uint32_t smb = smem_u32(sm);
    int tid = threadIdx.x, wid = tid >> 5, lane = tid & 31;
    int rowBase = blockIdx.x * 128, colBase = blockIdx.y * 128;
    int wm = (wid & 3) * 32;
    int wn = (wid >> 2) * 64;
    int lq = lane >> 2, lr = lane & 3;

    auto issue = [&](int ch) {
        int kc = ch * KCH;
        int buf = ch & 1;
        uint32_t asb = smb + (uint32_t)(buf * ABUF) * 4u;
        uint32_t wsb = smb + (uint32_t)(2 * ABUF + buf * WBUF) * 4u;
        #pragma unroll
        for (int i = 0; i < 4; i++) {
            int c = tid + i * 256;
            int r = c >> 3, kp = (c & 7) << 2;
            int gr = rowBase + r;
            const float* src = &A[(size_t)gr * K + kc + kp];
            uint32_t dst = asb + (uint32_t)(r * APITCH + kp) * 4u;
            int sz = (gr < N) ? 16 : 0;
            asm volatile("cp.async.ca.shared.global [%0], [%1], 16, %2;"
                         :: "r"(dst), "l"(src), "r"(sz));
        }
        #pragma unroll
        for (int i = 0; i < 4; i++) {
            int c = tid + i * 256;
            int rr = c >> 5, np = (c & 31) << 2;
            const float* src = &W[(size_t)(kc + rr) * ncols + colBase + np];
            uint32_t dst = wsb + (uint32_t)(rr * WPITCH + np) * 4u;
            asm volatile("cp.async.ca.shared.global [%0], [%1], 16;"
                         :: "r"(dst), "l"(src));
        }
        asm volatile("cp.async.commit_group;");
    };

    float acc[2][8][4];
    #pragma unroll
    for (int i = 0; i < 2; i++)
        #pragma unroll
        for (int j = 0; j < 8; j++)
            #pragma unroll
            for (int k = 0; k < 4; k++) acc[i][j][k] = 0.0f;

    int nch = K / KCH;
    issue(0);
    for (int ch = 0; ch < nch; ch++) {
        if (ch + 1 < nch) {
            issue(ch + 1);
            asm volatile("cp.async.wait_group 1;");
        } else {
            asm volatile("cp.async.wait_group 0;");
        }
        __syncthreads();
        const float* As = sm + (ch & 1) * ABUF;
        const float* Ws = sm + 2 * ABUF + (ch & 1) * WBUF;
        #pragma unroll
        for (int ks = 0; ks < KCH; ks += 8) {
            uint32_t a[2][4], b[8][2];
            #pragma unroll
            for (int mf = 0; mf < 2; mf++) {
                int r0 = wm + mf * 16 + lq;
                a[mf][0] = __float_as_uint(As[r0 * APITCH + ks + lr]);
                a[mf][1] = __float_as_uint(As[(r0 + 8) * APITCH + ks + lr]);
                a[mf][2] = __float_as_uint(As[r0 * APITCH + ks + lr + 4]);
                a[mf][3] = __float_as_uint(As[(r0 + 8) * APITCH + ks + lr + 4]);
            }
            #pragma unroll
            for (int nf = 0; nf < 8; nf++) {
                int c0 = wn + nf * 8 + lq;
                b[nf][0] = __float_as_uint(Ws[(ks + lr) * WPITCH + c0]);
                b[nf][1] = __float_as_uint(Ws[(ks + lr + 4) * WPITCH + c0]);
            }
            #pragma unroll
            for (int mf = 0; mf < 2; mf++)
                #pragma unroll
                for (int nf = 0; nf < 8; nf++)
                    MMA_TF32(acc[mf][nf], a[mf], b[nf]);
        }
        __syncthreads();
    }

    #pragma unroll
    for (int mf = 0; mf < 2; mf++) {
        int r0 = rowBase + wm + mf * 16 + lq;
        #pragma unroll
        for (int half = 0; half < 2; half++) {
            int row = r0 + half * 8;
            if (row >= N) continue;
            #pragma unroll
            for (int nf = 0; nf < 8; nf++) {
                int col = colBase + wn + nf * 8 + lr * 2;
                float2 r2 = *(const float2*)&res[(size_t)row * ncols + col];
                float v0 = r2.x + gelu_f(acc[mf][nf][half * 2]     + bias[col]);
                float v1 = r2.y + gelu_f(acc[mf][nf][half * 2 + 1] + bias[col + 1]);
                *(float2*)&out[(size_t)row * ncols + col] = make_float2(v0, v1);
            }
        }
    }
}

// ---------------- launch ----------------
extern "C" void kernel_launch(void* const* d_in, const int* in_sizes, int n_in,
                              void* d_out, int out_size) {
    const float* x    = (const float*)d_in[0];
    const void*  ei   = d_in[1];
    const float* ln1g = (const float*)d_in[3];
    const float* ln1b = (const float*)d_in[4];
    const float* Wc   = (const float*)d_in[5];
    const float* bc   = (const float*)d_in[6];
    const float* ln2g = (const float*)d_in[7];
    const float* ln2b = (const float*)d_in[8];
    const float* W1   = (const float*)d_in[9];
    const float* b1   = (const float*)d_in[10];
    const float* W2   = (const float*)d_in[11];
    const float* b2   = (const float*)d_in[12];
    float* out = (float*)d_out;

    int N = in_sizes[0] / D;
    int E = in_sizes[1] / 2;

    static int inited = 0;
    static cudaStream_t s2;
    static cudaEvent_t evFork, evJoin;
    if (!inited) {
        cudaFuncSetAttribute(k_gemm_tc, cudaFuncAttributeMaxDynamicSharedMemorySize, GEMM_SMEM);
        cudaFuncSetAttribute(k_gemm_hi, cudaFuncAttributeMaxDynamicSharedMemorySize, GEMMH_SMEM);
        cudaStreamCreateWithFlags(&s2, cudaStreamNonBlocking);
        cudaEventCreateWithFlags(&evFork, cudaEventDisableTiming);
        cudaEventCreateWithFlags(&evJoin, cudaEventDisableTiming);
        inited = 1;
    }

    float* gH;  cudaGetSymbolAddress((void**)&gH,  g_H);
    float* gHW; cudaGetSymbolAddress((void**)&gHW, g_HW);
    float* gF1; cudaGetSymbolAddress((void**)&gF1, g_F1);
    float* gWr; cudaGetSymbolAddress((void**)&gWr, g_Wr);

    dim3 lnBlk(32, 8);
    int lnGrid = (N + 7) / 8;
    int rowBlocks = (N + 127) / 128;
    int NB = (N + 1023) / 1024;

    // fork: side stream handles CSR build + W1/W2 prep
    cudaEventRecord(evFork, 0);
    cudaStreamWaitEvent(s2, evFork, 0);

    // 0. (s2) detect + zero degrees
    k_detect_init<<<(N + 255) / 256, 256, 0, s2>>>((const unsigned long long*)ei,
                                                   (long long)E, (unsigned long long)N, N);
    // 1. (main) round Wc
    k_prepwc<<<(D * D + 255) / 256, 256>>>(Wc);
    // 2. (main) H = tf32r(gelu(LN1(x)))
    k_rowln1<<<lnGrid, lnBlk>>>(x, ln1g, ln1b, gH, N);
    // 3. (main) HW = H @ Wc    <-- PROFILED LAUNCH
    k_gemm_hi<<<dim3(rowBlocks, 2), 256, GEMMH_SMEM>>>(
        gH, gWr + WR_WC, nullptr, gHW, N, D, D, 0);
    // 4-9. (s2) degree histogram -> scan -> fill -> W1/W2 prep
    k_degcount<<<(E + 255) / 256, 256, 0, s2>>>(ei, E);
    k_scan1<<<NB, 1024, 0, s2>>>(N);
    k_scan2<<<1, 128, 0, s2>>>(NB);
    k_scan3<<<(N + 256) / 256, 256, 0, s2>>>(N, E);
    k_fill<<<(E + 255) / 256, 256, 0, s2>>>(ei, E);
    k_prepw12<<<(D * D4 + 255) / 256, 256, 0, s2>>>(W1, W2);
    cudaEventRecord(evJoin, s2);

    // join: gather needs GEMM1 (main) + CSR/dinv (s2)
    cudaStreamWaitEvent(0, evJoin, 0);

    // 10. H = tf32r(LN2(x + agg + b_conv))
    {
        int wpb = 8;
        int blocks = (N + wpb - 1) / wpb;
        k_gather_ln2<<<blocks, wpb * 32>>>(x, bc, ln2g, ln2b, gH, N);
    }
    // 11. F1 = tf32r(gelu(H @ W1 + b1))
    k_gemm_hi<<<dim3(rowBlocks, 8), 256, GEMMH_SMEM>>>(
        gH, gWr + WR_W1, b1, gF1, N, D, D4, 1);
    // 12. out = x + gelu(F1 @ W2 + b2)
    k_gemm_tc<<<dim3(rowBlocks, 1), 256, GEMM_SMEM>>>(
        gF1, gWr + WR_W2, b2, x, out, N, D4, D);
}

// round 15
// speedup vs baseline: 1.0036x; 1.0036x over previous
#include <cuda_runtime.h>
#include <math.h>
#include <stdint.h>

#define D    128
#define D4   512
#define MAXN 100000
#define MAXE 1000000

// ---------------- scratch (no allocations allowed) ----------------
__device__ float g_H  [MAXN * D];    // gelu(LN1(x)) / LN2(conv), tf32-rounded
__device__ float g_HW [MAXN * D];    // h @ W_conv (raw fp32)
__device__ float g_F1 [MAXN * D4];   // FFN hidden, tf32-rounded
__device__ float g_Wr [D * D + 2 * D * D4];  // tf32-rounded Wc | W1 | W2
__device__ int   g_deg [MAXN];
__device__ int   g_scanI[MAXN];
__device__ int   g_bsum[128];
__device__ int   g_off [MAXN + 1];
__device__ int   g_pos [MAXN];
__device__ int   g_csr [MAXE];
__device__ float g_dinv[MAXN];
__device__ int   g_eflag;            // 1 => edge_index stored as int32

#define WR_WC 0
#define WR_W1 (D * D)
#define WR_W2 (D * D + D * D4)

__device__ __forceinline__ float gelu_f(float x) {
    return 0.5f * x * (1.0f + erff(x * 0.70710678118654752f));
}
__device__ __forceinline__ float tf32r(float x) {   // round to tf32 grid
    uint32_t r;
    asm("cvt.rna.tf32.f32 %0, %1;" : "=r"(r) : "f"(x));
    return __uint_as_float(r);
}
__device__ __forceinline__ uint32_t smem_u32(const void* p) {
    uint32_t a;
    asm("{ .reg .u64 t; cvta.to.shared.u64 t, %1; cvt.u32.u64 %0, t; }"
        : "=r"(a) : "l"(p));
    return a;
}
#define MMA_TF32(acc, a, b) \
    asm volatile( \
        "mma.sync.aligned.m16n8k8.row.col.f32.tf32.tf32.f32 " \
        "{%0,%1,%2,%3}, {%4,%5,%6,%7}, {%8,%9}, {%0,%1,%2,%3};" \
        : "+f"((acc)[0]), "+f"((acc)[1]), "+f"((acc)[2]), "+f"((acc)[3]) \
        : "r"((a)[0]), "r"((a)[1]), "r"((a)[2]), "r"((a)[3]), \
          "r"((b)[0]), "r"((b)[1]))

// ------- detect edge dtype + zero degree (side stream) -------
__global__ void k_detect_init(const unsigned long long* __restrict__ p, long long E,
                              unsigned long long NN, int N) {
    int i = blockIdx.x * blockDim.x + threadIdx.x;
    if (i < N) g_deg[i] = 0;
    if (blockIdx.x == 0) {
        __shared__ int bad;
        if (threadIdx.x == 0) bad = 0;
        __syncthreads();
        long long step = E / (long long)blockDim.x;
        if (step < 1) step = 1;
        long long idx = (long long)threadIdx.x * step;
        if (idx < E && p[idx] >= NN) bad = 1;
        __syncthreads();
        if (threadIdx.x == 0) g_eflag = bad;
    }
}

// ------- round Wc (main stream, before GEMM1) -------
__global__ void k_prepwc(const float* __restrict__ Wc) {
    int i = blockIdx.x * blockDim.x + threadIdx.x;
    if (i < D * D) g_Wr[WR_WC + i] = tf32r(Wc[i]);
}

// ------- round W1,W2 (side stream) -------
__global__ void k_prepw12(const float* __restrict__ W1, const float* __restrict__ W2) {
    int i = blockIdx.x * blockDim.x + threadIdx.x;
    if (i < D * D4) {
        g_Wr[WR_W1 + i] = tf32r(W1[i]);
        g_Wr[WR_W2 + i] = tf32r(W2[i]);
    }
}

// ---------------- LN1 + gelu (tf32-rounded output) ----------------
__global__ void k_rowln1(const float* __restrict__ x,
                         const float* __restrict__ g, const float* __restrict__ b,
                         float* __restrict__ out, int N) {
    int row = blockIdx.x * blockDim.y + threadIdx.y;
    if (row >= N) return;
    int l = threadIdx.x;
    float4 v = ((const float4*)(x + (size_t)row * D))[l];
    float s  = v.x + v.y + v.z + v.w;
    float ss = v.x*v.x + v.y*v.y + v.z*v.z + v.w*v.w;
    #pragma unroll
    for (int o = 16; o; o >>= 1) {
        s  += __shfl_xor_sync(0xffffffffu, s,  o);
        ss += __shfl_xor_sync(0xffffffffu, ss, o);
    }
    float mu  = s * (1.0f / D);
    float var = ss * (1.0f / D) - mu * mu;
    float rs  = rsqrtf(var + 1e-5f);
    float4 gg = ((const float4*)g)[l];
    float4 bb = ((const float4*)b)[l];
    float4 r;
    r.x = tf32r(gelu_f((v.x - mu) * rs * gg.x + bb.x));
    r.y = tf32r(gelu_f((v.y - mu) * rs * gg.y + bb.y));
    r.z = tf32r(gelu_f((v.z - mu) * rs * gg.z + bb.z));
    r.w = tf32r(gelu_f((v.w - mu) * rs * gg.w + bb.w));
    ((float4*)(out + (size_t)row * D))[l] = r;
}

// ---------------- degree histogram ----------------
__global__ void k_degcount(const void* __restrict__ ei, int E) {
    int e = blockIdx.x * blockDim.x + threadIdx.x;
    if (e >= E) return;
    int dst;
    if (g_eflag) dst = ((const int*)ei)[E + e];
    else         dst = (int)((const long long*)ei)[E + e];
    atomicAdd(&g_deg[dst], 1);
}

// ---------------- parallel 3-phase scan ----------------
__global__ void k_scan1(int N) {
    __shared__ int sm[1024];
    int i = blockIdx.x * 1024 + threadIdx.x;
    int v = (i < N) ? g_deg[i] : 0;
    sm[threadIdx.x] = v;
    __syncthreads();
    #pragma unroll
    for (int off = 1; off < 1024; off <<= 1) {
        int t = (threadIdx.x >= off) ? sm[threadIdx.x - off] : 0;
        __syncthreads();
        sm[threadIdx.x] += t;
        __syncthreads();
    }
    if (i < N) g_scanI[i] = sm[threadIdx.x];
    if (threadIdx.x == 1023) g_bsum[blockIdx.x] = sm[1023];
}
__global__ void k_scan2(int NB) {
    __shared__ int sm[128];
    int t = threadIdx.x;
    sm[t] = (t < NB) ? g_bsum[t] : 0;
    __syncthreads();
    #pragma unroll
    for (int off = 1; off < 128; off <<= 1) {
        int v = (t >= off) ? sm[t - off] : 0;
        __syncthreads();
        sm[t] += v;
        __syncthreads();
    }
    if (t < NB) g_bsum[t] = sm[t];
}
__global__ void k_scan3(int N, int E) {
    int i = blockIdx.x * blockDim.x + threadIdx.x;
    if (i > N) return;
    if (i == N) { g_off[N] = E; return; }
    int blk = i >> 10;
    int base = blk ? g_bsum[blk - 1] : 0;
    int d = g_deg[i];
    int off = base + g_scanI[i] - d;
    g_off[i] = off;
    g_pos[i] = off;
    g_dinv[i] = rsqrtf((float)(d + 1));
}

// ---------------- CSR fill ----------------
__global__ void k_fill(const void* __restrict__ ei, int E) {
    int e = blockIdx.x * blockDim.x + threadIdx.x;
    if (e >= E) return;
    int s, d2;
    if (g_eflag) { const int* p = (const int*)ei; s = p[e]; d2 = p[E + e]; }
    else { const long long* p = (const long long*)ei; s = (int)p[e]; d2 = (int)p[E + e]; }
    int pos = atomicAdd(&g_pos[d2], 1);
    g_csr[pos] = s;
}

// ------- gather (MLP=4) fused with LN2 (tf32-rounded output) -------
__global__ void k_gather_ln2(const float* __restrict__ x,
                             const float* __restrict__ bconv,
                             const float* __restrict__ g, const float* __restrict__ b,
                             float* __restrict__ out, int N) {
    int row = blockIdx.x * (blockDim.x >> 5) + (threadIdx.x >> 5);
    if (row >= N) return;
    int lane = threadIdx.x & 31;
    float di = g_dinv[row];
    float4 acc = ((const float4*)g_HW)[row * 32 + lane];   // self term
    acc.x *= di; acc.y *= di; acc.z *= di; acc.w *= di;
    int e = g_off[row], e1 = g_off[row + 1];
    for (; e + 4 <= e1; e += 4) {
        int s0 = g_csr[e], s1 = g_csr[e + 1], s2 = g_csr[e + 2], s3 = g_csr[e + 3];
        float c0 = g_dinv[s0], c1 = g_dinv[s1], c2 = g_dinv[s2], c3 = g_dinv[s3];
        float4 v0 = ((const float4*)g_HW)[s0 * 32 + lane];
        float4 v1 = ((const float4*)g_HW)[s1 * 32 + lane];
        float4 v2 = ((const float4*)g_HW)[s2 * 32 + lane];
        float4 v3 = ((const float4*)g_HW)[s3 * 32 + lane];
        acc.x += (v0.x*c0 + v1.x*c1) + (v2.x*c2 + v3.x*c3);
        acc.y += (v0.y*c0 + v1.y*c1) + (v2.y*c2 + v3.y*c3);
        acc.z += (v0.z*c0 + v1.z*c1) + (v2.z*c2 + v3.z*c3);
        acc.w += (v0.w*c0 + v1.w*c1) + (v2.w*c2 + v3.w*c3);
    }
    for (; e < e1; e++) {
        int s = g_csr[e];
        float c = g_dinv[s];
        float4 v = ((const float4*)g_HW)[s * 32 + lane];
        acc.x += v.x*c; acc.y += v.y*c; acc.z += v.z*c; acc.w += v.w*c;
    }
    float4 xv  = ((const float4*)x)[row * 32 + lane];
    float4 bcv = ((const float4*)bconv)[lane];
    float4 v;
    v.x = xv.x + acc.x * di + bcv.x;
    v.y = xv.y + acc.y * di + bcv.y;
    v.z = xv.z + acc.z * di + bcv.z;
    v.w = xv.w + acc.w * di + bcv.w;
    float s  = v.x + v.y + v.z + v.w;
    float ss = v.x*v.x + v.y*v.y + v.z*v.z + v.w*v.w;
    #pragma unroll
    for (int o = 16; o; o >>= 1) {
        s  += __shfl_xor_sync(0xffffffffu, s,  o);
        ss += __shfl_xor_sync(0xffffffffu, ss, o);
    }
    float mu  = s * (1.0f / D);
    float var = ss * (1.0f / D) - mu * mu;
    float rs  = rsqrtf(var + 1e-5f);
    float4 gg = ((const float4*)g)[lane];
    float4 bb = ((const float4*)b)[lane];
    float4 r;
    r.x = tf32r((v.x - mu) * rs * gg.x + bb.x);
    r.y = tf32r((v.y - mu) * rs * gg.y + bb.y);
    r.z = tf32r((v.z - mu) * rs * gg.z + bb.z);
    r.w = tf32r((v.w - mu) * rs * gg.w + bb.w);
    ((float4*)(out + (size_t)row * D))[lane] = r;
}

// ---- hi-occupancy tf32 GEMM: CTA tile 128x64, 3 CTA/SM ----
// warps 4(m)x2(n), warp tile 32x32. mode 0: raw. 1: tf32r(gelu(acc+bias)).
#define KCH 32
#define APITCH 36
#define WPITCH2 72
#define ABUF2 (128 * APITCH)
#define WBUF2 (KCH * WPITCH2)
#define GEMMH_SMEM ((2 * (ABUF2 + WBUF2)) * (int)sizeof(float))

__global__ void __launch_bounds__(256, 3) k_gemm_hi(
    const float* __restrict__ A, const float* __restrict__ W,
    const float* __restrict__ bias,
    float* __restrict__ out, int N, int K, int ncols, int mode)
{
    extern __shared__ float sm[];
    uint32_t smb = smem_u32(sm);
    int tid = threadIdx.x, wid = tid >> 5, lane = tid & 31;
    int rowBase = blockIdx.x * 128, colBase = blockIdx.y * 64;
    int wm = (wid & 3) * 32;
    int wn = (wid >> 2) * 32;
    int lq = lane >> 2, lr = lane & 3;

    auto issue = [&](int ch) {
        int kc = ch * KCH;
        int buf = ch & 1;
        uint32_t asb = smb + (uint32_t)(buf * ABUF2) * 4u;
        uint32_t wsb = smb + (uint32_t)(2 * ABUF2 + buf * WBUF2) * 4u;
        #pragma unroll
        for (int i = 0; i < 4; i++) {
            int c = tid + i * 256;            // A: 1024 chunks of 16B
            int r = c >> 3, kp = (c & 7) << 2;
            int gr = rowBase + r;
            const float* src = &A[(size_t)gr * K + kc + kp];
            uint32_t dst = asb + (uint32_t)(r * APITCH + kp) * 4u;
            int sz = (gr < N) ? 16 : 0;
            asm volatile("cp.async.ca.shared.global [%0], [%1], 16, %2;"
                         :: "r"(dst), "l"(src), "r"(sz));
        }
        #pragma unroll
        for (int i = 0; i < 2; i++) {
            int c = tid + i * 256;            // W: 512 chunks of 16B (32 x 64)
            int rr = c >> 4, np = (c & 15) << 2;
            const float* src = &W[(size_t)(kc + rr) * ncols + colBase + np];
            uint32_t dst = wsb + (uint32_t)(rr * WPITCH2 + np) * 4u;
            asm volatile("cp.async.ca.shared.global [%0], [%1], 16;"
                         :: "r"(dst), "l"(src));
        }
        asm volatile("cp.async.commit_group;");
    };

    float acc[2][4][4];
    #pragma unroll
    for (int i = 0; i < 2; i++)
        #pragma unroll
        for (int j = 0; j < 4; j++)
            #pragma unroll
            for (int k = 0; k < 4; k++) acc[i][j][k] = 0.0f;

    int nch = K / KCH;
    issue(0);
    for (int ch = 0; ch < nch; ch++) {
        if (ch + 1 < nch) {
            issue(ch + 1);
            asm volatile("cp.async.wait_group 1;");
        } else {
            asm volatile("cp.async.wait_group 0;");
        }
        __syncthreads();
        const float* As = sm + (ch & 1) * ABUF2;
        const float* Ws = sm + 2 * ABUF2 + (ch & 1) * WBUF2;
        #pragma unroll
        for (int ks = 0; ks < KCH; ks += 8) {
            uint32_t a[2][4], b[4][2];
            #pragma unroll
            for (int mf = 0; mf < 2; mf++) {
                int r0 = wm + mf * 16 + lq;
                a[mf][0] = __float_as_uint(As[r0 * APITCH + ks + lr]);
                a[mf][1] = __float_as_uint(As[(r0 + 8) * APITCH + ks + lr]);
                a[mf][2] = __float_as_uint(As[r0 * APITCH + ks + lr + 4]);
                a[mf][3] = __float_as_uint(As[(r0 + 8) * APITCH + ks + lr + 4]);
            }
            #pragma unroll
            for (int nf = 0; nf < 4; nf++) {
                int c0 = wn + nf * 8 + lq;
                b[nf][0] = __float_as_uint(Ws[(ks + lr) * WPITCH2 + c0]);
                b[nf][1] = __float_as_uint(Ws[(ks + lr + 4) * WPITCH2 + c0]);
            }
            #pragma unroll
            for (int mf = 0; mf < 2; mf++)
                #pragma unroll
                for (int nf = 0; nf < 4; nf++)
                    MMA_TF32(acc[mf][nf], a[mf], b[nf]);
        }
        __syncthreads();
    }

    #pragma unroll
    for (int mf = 0; mf < 2; mf++) {
        int r0 = rowBase + wm + mf * 16 + lq;
        #pragma unroll
        for (int half = 0; half < 2; half++) {
            int row = r0 + half * 8;
            if (row >= N) continue;
            #pragma unroll
            for (int nf = 0; nf < 4; nf++) {
                int col = colBase + wn + nf * 8 + lr * 2;
                float v0 = acc[mf][nf][half * 2];
                float v1 = acc[mf][nf][half * 2 + 1];
                if (mode == 1) {
                    v0 = tf32r(gelu_f(v0 + bias[col]));
                    v1 = tf32r(gelu_f(v1 + bias[col + 1]));
                }
                *(float2*)&out[(size_t)row * ncols + col] = make_float2(v0, v1);
            }
        }
    }
}

// ---- wide tf32 GEMM (R10): CTA tile 128x128, 2 CTA/SM. For GEMM3 only ----
// mode 2: res + gelu(acc+bias).
#define WPITCH 136
#define ABUF (128 * APITCH)
#define WBUF (KCH * WPITCH)
#define GEMM_SMEM ((2 * (ABUF + WBUF)) * (int)sizeof(float))

__global__ void __launch_bounds__(256, 2) k_gemm_tc(
    const float* __restrict__ A, const float* __restrict__ W,
    const float* __restrict__ bias, const float* __restrict__ res,
    float* __restrict__ out, int N, int K, int ncols)
{
    extern __shared__ float sm[];
    uint32_t smb = smem_u32(sm);
    int tid = threadIdx.x, wid = tid >> 5, lane = tid & 31;
    int rowBase = blockIdx.x * 128, colBase = blockIdx.y * 128;
    int wm = (wid & 3) * 32;
    int wn = (wid >> 2) * 64;
    int lq = lane >> 2, lr = lane & 3;

    auto issue = [&](int ch) {
        int kc = ch * KCH;
        int buf = ch & 1;
        uint32_t asb = smb + (uint32_t)(buf * ABUF) * 4u;
        uint32_t wsb = smb + (uint32_t)(2 * ABUF + buf * WBUF) * 4u;
        #pragma unroll
        for (int i = 0; i < 4; i++) {
            int c = tid + i * 256;
            int r = c >> 3, kp = (c & 7) << 2;
            int gr = rowBase + r;
            const float* src = &A[(size_t)gr * K + kc + kp];
            uint32_t dst = asb + (uint32_t)(r * APITCH + kp) * 4u;
            int sz = (gr < N) ? 16 : 0;
            asm volatile("cp.async.ca.shared.global [%0], [%1], 16, %2;"
                         :: "r"(dst), "l"(src), "r"(sz));
        }
        #pragma unroll
        for (int i = 0; i < 4; i++) {
            int c = tid + i * 256;
            int rr = c >> 5, np = (c & 31) << 2;
            const float* src = &W[(size_t)(kc + rr) * ncols + colBase + np];
            uint32_t dst = wsb + (uint32_t)(rr * WPITCH + np) * 4u;
            asm volatile("cp.async.ca.shared.global [%0], [%1], 16;"
                         :: "r"(dst), "l"(src));
        }
        asm volatile("cp.async.commit_group;");
    };

    float acc[2][8][4];
    #pragma unroll
    for (int i = 0; i < 2; i++)
        #pragma unroll
        for (int j = 0; j < 8; j++)
            #pragma unroll
            for (int k = 0; k < 4; k++) acc[i][j][k] = 0.0f;

    int nch = K / KCH;
    issue(0);
    for (int ch = 0; ch < nch; ch++) {
        if (ch + 1 < nch) {
            issue(ch + 1);
            asm volatile("cp.async.wait_group 1;");
        } else {
            asm volatile("cp.async.wait_group 0;");
        }
        __syncthreads();
        const float* As = sm + (ch & 1) * ABUF;
        const float* Ws = sm + 2 * ABUF + (ch & 1) * WBUF;
        #pragma unroll
        for (int ks = 0; ks < KCH; ks += 8) {
            uint32_t a[2][4], b[8][2];
            #pragma unroll
            for (int mf = 0; mf < 2; mf++) {
                int r0 = wm + mf * 16 + lq;
                a[mf][0] = __float_as_uint(As[r0 * APITCH + ks + lr]);
                a[mf][1] = __float_as_uint(As[(r0 + 8) * APITCH + ks + lr]);
                a[mf][2] = __float_as_uint(As[r0 * APITCH + ks + lr + 4]);
                a[mf][3] = __float_as_uint(As[(r0 + 8) * APITCH + ks + lr + 4]);
            }
            #pragma unroll
            for (int nf = 0; nf < 8; nf++) {
                int c0 = wn + nf * 8 + lq;
                b[nf][0] = __float_as_uint(Ws[(ks + lr) * WPITCH + c0]);
                b[nf][1] = __float_as_uint(Ws[(ks + lr + 4) * WPITCH + c0]);
            }
            #pragma unroll
            for (int mf = 0; mf < 2; mf++)
                #pragma unroll
                for (int nf = 0; nf < 8; nf++)
                    MMA_TF32(acc[mf][nf], a[mf], b[nf]);
        }
        __syncthreads();
    }

    #pragma unroll
    for (int mf = 0; mf < 2; mf++) {
        int r0 = rowBase + wm + mf * 16 + lq;
        #pragma unroll
        for (int half = 0; half < 2; half++) {
            int row = r0 + half * 8;
            if (row >= N) continue;
            #pragma unroll
            for (int nf = 0; nf < 8; nf++) {
                int col = colBase + wn + nf * 8 + lr * 2;
                float2 r2 = *(const float2*)&res[(size_t)row * ncols + col];
                float v0 = r2.x + gelu_f(acc[mf][nf][half * 2]     + bias[col]);
                float v1 = r2.y + gelu_f(acc[mf][nf][half * 2 + 1] + bias[col + 1]);
                *(float2*)&out[(size_t)row * ncols + col] = make_float2(v0, v1);
            }
        }
    }
}

// ---------------- launch ----------------
extern "C" void kernel_launch(void* const* d_in, const int* in_sizes, int n_in,
                              void* d_out, int out_size) {
    const float* x    = (const float*)d_in[0];
    const void*  ei   = d_in[1];
    const float* ln1g = (const float*)d_in[3];
    const float* ln1b = (const float*)d_in[4];
    const float* Wc   = (const float*)d_in[5];
    const float* bc   = (const float*)d_in[6];
    const float* ln2g = (const float*)d_in[7];
    const float* ln2b = (const float*)d_in[8];
    const float* W1   = (const float*)d_in[9];
    const float* b1   = (const float*)d_in[10];
    const float* W2   = (const float*)d_in[11];
    const float* b2   = (const float*)d_in[12];
    float* out = (float*)d_out;

    int N = in_sizes[0] / D;
    int E = in_sizes[1] / 2;

    static int inited = 0;
    static cudaStream_t s2;
    static cudaEvent_t evFork, evJoin;
    if (!inited) {
        cudaFuncSetAttribute(k_gemm_tc, cudaFuncAttributeMaxDynamicSharedMemorySize, GEMM_SMEM);
        cudaFuncSetAttribute(k_gemm_hi, cudaFuncAttributeMaxDynamicSharedMemorySize, GEMMH_SMEM);
        cudaStreamCreateWithFlags(&s2, cudaStreamNonBlocking);
        cudaEventCreateWithFlags(&evFork, cudaEventDisableTiming);
        cudaEventCreateWithFlags(&evJoin, cudaEventDisableTiming);
        inited = 1;
    }

    float* gH;  cudaGetSymbolAddress((void**)&gH,  g_H);
    float* gHW; cudaGetSymbolAddress((void**)&gHW, g_HW);
    float* gF1; cudaGetSymbolAddress((void**)&gF1, g_F1);
    float* gWr; cudaGetSymbolAddress((void**)&gWr, g_Wr);

    dim3 lnBlk(32, 8);
    int lnGrid = (N + 7) / 8;
    int rowBlocks = (N + 127) / 128;
    int NB = (N + 1023) / 1024;

    // fork: side stream handles CSR build + W1/W2 prep
    cudaEventRecord(evFork, 0);
    cudaStreamWaitEvent(s2, evFork, 0);

    // 0. (s2) detect + zero degrees
    k_detect_init<<<(N + 255) / 256, 256, 0, s2>>>((const unsigned long long*)ei,
                                                   (long long)E, (unsigned long long)N, N);
    // 1. (main) round Wc
    k_prepwc<<<(D * D + 255) / 256, 256>>>(Wc);
    // 2. (main) H = tf32r(gelu(LN1(x)))
    k_rowln1<<<lnGrid, lnBlk>>>(x, ln1g, ln1b, gH, N);
    // 3. (main) HW = H @ Wc    <-- PROFILED LAUNCH
    k_gemm_hi<<<dim3(rowBlocks, 2), 256, GEMMH_SMEM>>>(
        gH, gWr + WR_WC, nullptr, gHW, N, D, D, 0);
    // 4-9. (s2) degree histogram -> scan -> fill -> W1/W2 prep
    k_degcount<<<(E + 255) / 256, 256, 0, s2>>>(ei, E);
    k_scan1<<<NB, 1024, 0, s2>>>(N);
    k_scan2<<<1, 128, 0, s2>>>(NB);
    k_scan3<<<(N + 256) / 256, 256, 0, s2>>>(N, E);
    k_fill<<<(E + 255) / 256, 256, 0, s2>>>(ei, E);
    k_prepw12<<<(D * D4 + 255) / 256, 256, 0, s2>>>(W1, W2);
    cudaEventRecord(evJoin, s2);

    // join: gather needs GEMM1 (main) + CSR/dinv (s2)
    cudaStreamWaitEvent(0, evJoin, 0);

    // 10. H = tf32r(LN2(x + agg + b_conv))
    {
        int wpb = 8;
        int blocks = (N + wpb - 1) / wpb;
        k_gather_ln2<<<blocks, wpb * 32>>>(x, bc, ln2g, ln2b, gH, N);
    }
    // 11. F1 = tf32r(gelu(H @ W1 + b1))
    k_gemm_hi<<<dim3(rowBlocks, 8), 256, GEMMH_SMEM>>>(
        gH, gWr + WR_W1, b1, gF1, N, D, D4, 1);
    // 12. out = x + gelu(F1 @ W2 + b2)
    k_gemm_tc<<<dim3(rowBlocks, 1), 256, GEMM_SMEM>>>(
        gF1, gWr + WR_W2, b2, x, out, N, D4, D);
}

// round 16
// speedup vs baseline: 1.0720x; 1.0682x over previous
#include <cuda_runtime.h>
#include <cuda_fp16.h>
#include <math.h>
#include <stdint.h>

#define D    128
#define D4   512
#define MAXN 100000
#define MAXE 1000000

// ---------------- scratch (no allocations allowed) ----------------
__device__ float  g_H  [MAXN * D];   // gelu(LN1(x)) / LN2(conv), tf32-rounded
__device__ float  g_HW [MAXN * D];   // h @ W_conv (raw fp32)
__device__ __half g_F1h[MAXN * D4];  // FFN hidden, fp16 (== tf32-rounded values)
__device__ float  g_Wr [D * D + 2 * D * D4];  // tf32-rounded Wc | W1 | W2
__device__ int    g_deg [MAXN];
__device__ int    g_scanI[MAXN];
__device__ int    g_bsum[128];
__device__ int    g_off [MAXN + 1];
__device__ int    g_pos [MAXN];
__device__ int    g_csr [MAXE];
__device__ float  g_dinv[MAXN];
__device__ int    g_eflag;           // 1 => edge_index stored as int32

#define WR_WC 0
#define WR_W1 (D * D)
#define WR_W2 (D * D + D * D4)

__device__ __forceinline__ float gelu_f(float x) {
    return 0.5f * x * (1.0f + erff(x * 0.70710678118654752f));
}
__device__ __forceinline__ float tf32r(float x) {   // round to tf32 grid
    uint32_t r;
    asm("cvt.rna.tf32.f32 %0, %1;" : "=r"(r) : "f"(x));
    return __uint_as_float(r);
}
__device__ __forceinline__ uint32_t smem_u32(const void* p) {
    uint32_t a;
    asm("{ .reg .u64 t; cvta.to.shared.u64 t, %1; cvt.u32.u64 %0, t; }"
        : "=r"(a) : "l"(p));
    return a;
}
#define MMA_TF32(acc, a, b) \
    asm volatile( \
        "mma.sync.aligned.m16n8k8.row.col.f32.tf32.tf32.f32 " \
        "{%0,%1,%2,%3}, {%4,%5,%6,%7}, {%8,%9}, {%0,%1,%2,%3};" \
        : "+f"((acc)[0]), "+f"((acc)[1]), "+f"((acc)[2]), "+f"((acc)[3]) \
        : "r"((a)[0]), "r"((a)[1]), "r"((a)[2]), "r"((a)[3]), \
          "r"((b)[0]), "r"((b)[1]))

// ------- detect edge dtype + zero degree (side stream) -------
__global__ void k_detect_init(const unsigned long long* __restrict__ p, long long E,
                              unsigned long long NN, int N) {
    int i = blockIdx.x * blockDim.x + threadIdx.x;
    if (i < N) g_deg[i] = 0;
    if (blockIdx.x == 0) {
        __shared__ int bad;
        if (threadIdx.x == 0) bad = 0;
        __syncthreads();
        long long step = E / (long long)blockDim.x;
        if (step < 1) step = 1;
        long long idx = (long long)threadIdx.x * step;
        if (idx < E && p[idx] >= NN) bad = 1;
        __syncthreads();
        if (threadIdx.x == 0) g_eflag = bad;
    }
}

// ------- round Wc (main stream, before GEMM1) -------
__global__ void k_prepwc(const float* __restrict__ Wc) {
    int i = blockIdx.x * blockDim.x + threadIdx.x;
    if (i < D * D) g_Wr[WR_WC + i] = tf32r(Wc[i]);
}

// ------- round W1,W2 (side stream) -------
__global__ void k_prepw12(const float* __restrict__ W1, const float* __restrict__ W2) {
    int i = blockIdx.x * blockDim.x + threadIdx.x;
    if (i < D * D4) {
        g_Wr[WR_W1 + i] = tf32r(W1[i]);
        g_Wr[WR_W2 + i] = tf32r(W2[i]);
    }
}

// ---------------- LN1 + gelu (tf32-rounded output) ----------------
__global__ void k_rowln1(const float* __restrict__ x,
                         const float* __restrict__ g, const float* __restrict__ b,
                         float* __restrict__ out, int N) {
    int row = blockIdx.x * blockDim.y + threadIdx.y;
    if (row >= N) return;
    int l = threadIdx.x;
    float4 v = ((const float4*)(x + (size_t)row * D))[l];
    float s  = v.x + v.y + v.z + v.w;
    float ss = v.x*v.x + v.y*v.y + v.z*v.z + v.w*v.w;
    #pragma unroll
    for (int o = 16; o; o >>= 1) {
        s  += __shfl_xor_sync(0xffffffffu, s,  o);
        ss += __shfl_xor_sync(0xffffffffu, ss, o);
    }
    float mu  = s * (1.0f / D);
    float var = ss * (1.0f / D) - mu * mu;
    float rs  = rsqrtf(var + 1e-5f);
    float4 gg = ((const float4*)g)[l];
    float4 bb = ((const float4*)b)[l];
    float4 r;
    r.x = tf32r(gelu_f((v.x - mu) * rs * gg.x + bb.x));
    r.y = tf32r(gelu_f((v.y - mu) * rs * gg.y + bb.y));
    r.z = tf32r(gelu_f((v.z - mu) * rs * gg.z + bb.z));
    r.w = tf32r(gelu_f((v.w - mu) * rs * gg.w + bb.w));
    ((float4*)(out + (size_t)row * D))[l] = r;
}

// ---------------- degree histogram ----------------
__global__ void k_degcount(const void* __restrict__ ei, int E) {
    int e = blockIdx.x * blockDim.x + threadIdx.x;
    if (e >= E) return;
    int dst;
    if (g_eflag) dst = ((const int*)ei)[E + e];
    else         dst = (int)((const long long*)ei)[E + e];
    atomicAdd(&g_deg[dst], 1);
}

// ---------------- parallel 3-phase scan ----------------
__global__ void k_scan1(int N) {
    __shared__ int sm[1024];
    int i = blockIdx.x * 1024 + threadIdx.x;
    int v = (i < N) ? g_deg[i] : 0;
    sm[threadIdx.x] = v;
    __syncthreads();
    #pragma unroll
    for (int off = 1; off < 1024; off <<= 1) {
        int t = (threadIdx.x >= off) ? sm[threadIdx.x - off] : 0;
        __syncthreads();
        sm[threadIdx.x] += t;
        __syncthreads();
    }
    if (i < N) g_scanI[i] = sm[threadIdx.x];
    if (threadIdx.x == 1023) g_bsum[blockIdx.x] = sm[1023];
}
__global__ void k_scan2(int NB) {
    __shared__ int sm[128];
    int t = threadIdx.x;
    sm[t] = (t < NB) ? g_bsum[t] : 0;
    __syncthreads();
    #pragma unroll
    for (int off = 1; off < 128; off <<= 1) {
        int v = (t >= off) ? sm[t - off] : 0;
        __syncthreads();
        sm[t] += v;
        __syncthreads();
    }
    if (t < NB) g_bsum[t] = sm[t];
}
__global__ void k_scan3(int N, int E) {
    int i = blockIdx.x * blockDim.x + threadIdx.x;
    if (i > N) return;
    if (i == N) { g_off[N] = E; return; }
    int blk = i >> 10;
    int base = blk ? g_bsum[blk - 1] : 0;
    int d = g_deg[i];
    int off = base + g_scanI[i] - d;
    g_off[i] = off;
    g_pos[i] = off;
    g_dinv[i] = rsqrtf((float)(d + 1));
}

// ---------------- CSR fill ----------------
__global__ void k_fill(const void* __restrict__ ei, int E) {
    int e = blockIdx.x * blockDim.x + threadIdx.x;
    if (e >= E) return;
    int s, d2;
    if (g_eflag) { const int* p = (const int*)ei; s = p[e]; d2 = p[E + e]; }
    else { const long long* p = (const long long*)ei; s = (int)p[e]; d2 = (int)p[E + e]; }
    int pos = atomicAdd(&g_pos[d2], 1);
    g_csr[pos] = s;
}

// ------- gather (MLP=4) fused with LN2 (tf32-rounded output) -------
__global__ void k_gather_ln2(const float* __restrict__ x,
                             const float* __restrict__ bconv,
                             const float* __restrict__ g, const float* __restrict__ b,
                             float* __restrict__ out, int N) {
    int row = blockIdx.x * (blockDim.x >> 5) + (threadIdx.x >> 5);
    if (row >= N) return;
    int lane = threadIdx.x & 31;
    float di = g_dinv[row];
    float4 acc = ((const float4*)g_HW)[row * 32 + lane];   // self term
    acc.x *= di; acc.y *= di; acc.z *= di; acc.w *= di;
    int e = g_off[row], e1 = g_off[row + 1];
    for (; e + 4 <= e1; e += 4) {
        int s0 = g_csr[e], s1 = g_csr[e + 1], s2 = g_csr[e + 2], s3 = g_csr[e + 3];
        float c0 = g_dinv[s0], c1 = g_dinv[s1], c2 = g_dinv[s2], c3 = g_dinv[s3];
        float4 v0 = ((const float4*)g_HW)[s0 * 32 + lane];
        float4 v1 = ((const float4*)g_HW)[s1 * 32 + lane];
        float4 v2 = ((const float4*)g_HW)[s2 * 32 + lane];
        float4 v3 = ((const float4*)g_HW)[s3 * 32 + lane];
        acc.x += (v0.x*c0 + v1.x*c1) + (v2.x*c2 + v3.x*c3);
        acc.y += (v0.y*c0 + v1.y*c1) + (v2.y*c2 + v3.y*c3);
        acc.z += (v0.z*c0 + v1.z*c1) + (v2.z*c2 + v3.z*c3);
        acc.w += (v0.w*c0 + v1.w*c1) + (v2.w*c2 + v3.w*c3);
    }
    for (; e < e1; e++) {
        int s = g_csr[e];
        float c = g_dinv[s];
        float4 v = ((const float4*)g_HW)[s * 32 + lane];
        acc.x += v.x*c; acc.y += v.y*c; acc.z += v.z*c; acc.w += v.w*c;
    }
    float4 xv  = ((const float4*)x)[row * 32 + lane];
    float4 bcv = ((const float4*)bconv)[lane];
    float4 v;
    v.x = xv.x + acc.x * di + bcv.x;
    v.y = xv.y + acc.y * di + bcv.y;
    v.z = xv.z + acc.z * di + bcv.z;
    v.w = xv.w + acc.w * di + bcv.w;
    float s  = v.x + v.y + v.z + v.w;
    float ss = v.x*v.x + v.y*v.y + v.z*v.z + v.w*v.w;
    #pragma unroll
    for (int o = 16; o; o >>= 1) {
        s  += __shfl_xor_sync(0xffffffffu, s,  o);
        ss += __shfl_xor_sync(0xffffffffu, ss, o);
    }
    float mu  = s * (1.0f / D);
    float var = ss * (1.0f / D) - mu * mu;
    float rs  = rsqrtf(var + 1e-5f);
    float4 gg = ((const float4*)g)[lane];
    float4 bb = ((const float4*)b)[lane];
    float4 r;
    r.x = tf32r((v.x - mu) * rs * gg.x + bb.x);
    r.y = tf32r((v.y - mu) * rs * gg.y + bb.y);
    r.z = tf32r((v.z - mu) * rs * gg.z + bb.z);
    r.w = tf32r((v.w - mu) * rs * gg.w + bb.w);
    ((float4*)(out + (size_t)row * D))[lane] = r;
}

// ---- wide tf32 GEMM (R13 structure): 128x128 tile, 2-stage, 2 CTA/SM ----
// mode 0: raw fp32 out. mode 1: gelu(acc+bias) -> fp16 out (11-bit grid).
#define KCH 32
#define APITCH 36
#define WPITCH 136
#define ABUF (128 * APITCH)
#define WBUF (KCH * WPITCH)
#define GEMM_SMEM ((2 * (ABUF + WBUF)) * (int)sizeof(float))

__global__ void __launch_bounds__(256, 2) k_gemm_tc(
    const float* __restrict__ A, const float* __restrict__ W,
    const float* __restrict__ bias,
    float* __restrict__ outf, __half* __restrict__ outh,
    int N, int K, int ncols, int mode)
{
    extern __shared__ float sm[];
    uint32_t smb = smem_u32(sm);
    int tid = threadIdx.x, wid = tid >> 5, lane = tid & 31;
    int rowBase = blockIdx.x * 128, colBase = blockIdx.y * 128;
    int wm = (wid & 3) * 32;
    int wn = (wid >> 2) * 64;
    int lq = lane >> 2, lr = lane & 3;

    auto issue = [&](int ch) {
        int kc = ch * KCH;
        int buf = ch & 1;
        uint32_t asb = smb + (uint32_t)(buf * ABUF) * 4u;
        uint32_t wsb = smb + (uint32_t)(2 * ABUF + buf * WBUF) * 4u;
        #pragma unroll
        for (int i = 0; i < 4; i++) {
            int c = tid + i * 256;
            int r = c >> 3, kp = (c & 7) << 2;
            int gr = rowBase + r;
            const float* src = &A[(size_t)gr * K + kc + kp];
            uint32_t dst = asb + (uint32_t)(r * APITCH + kp) * 4u;
            int sz = (gr < N) ? 16 : 0;
            asm volatile("cp.async.ca.shared.global [%0], [%1], 16, %2;"
                         :: "r"(dst), "l"(src), "r"(sz));
        }
        #pragma unroll
        for (int i = 0; i < 4; i++) {
            int c = tid + i * 256;
            int rr = c >> 5, np = (c & 31) << 2;
            const float* src = &W[(size_t)(kc + rr) * ncols + colBase + np];
            uint32_t dst = wsb + (uint32_t)(rr * WPITCH + np) * 4u;
            asm volatile("cp.async.ca.shared.global [%0], [%1], 16;"
                         :: "r"(dst), "l"(src));
        }
        asm volatile("cp.async.commit_group;");
    };

    float acc[2][8][4];
    #pragma unroll
    for (int i = 0; i < 2; i++)
        #pragma unroll
        for (int j = 0; j < 8; j++)
            #pragma unroll
            for (int k = 0; k < 4; k++) acc[i][j][k] = 0.0f;

    int nch = K / KCH;
    issue(0);
    for (int ch = 0; ch < nch; ch++) {
        if (ch + 1 < nch) {
            issue(ch + 1);
            asm volatile("cp.async.wait_group 1;");
        } else {
            asm volatile("cp.async.wait_group 0;");
        }
        __syncthreads();
        const float* As = sm + (ch & 1) * ABUF;
        const float* Ws = sm + 2 * ABUF + (ch & 1) * WBUF;
        #pragma unroll
        for (int ks = 0; ks < KCH; ks += 8) {
            uint32_t a[2][4], b[8][2];
            #pragma unroll
            for (int mf = 0; mf < 2; mf++) {
                int r0 = wm + mf * 16 + lq;
                a[mf][0] = __float_as_uint(As[r0 * APITCH + ks + lr]);
                a[mf][1] = __float_as_uint(As[(r0 + 8) * APITCH + ks + lr]);
                a[mf][2] = __float_as_uint(As[r0 * APITCH + ks + lr + 4]);
                a[mf][3] = __float_as_uint(As[(r0 + 8) * APITCH + ks + lr + 4]);
            }
            #pragma unroll
            for (int nf = 0; nf < 8; nf++) {
                int c0 = wn + nf * 8 + lq;
                b[nf][0] = __float_as_uint(Ws[(ks + lr) * WPITCH + c0]);
                b[nf][1] = __float_as_uint(Ws[(ks + lr + 4) * WPITCH + c0]);
            }
            #pragma unroll
            for (int mf = 0; mf < 2; mf++)
                #pragma unroll
                for (int nf = 0; nf < 8; nf++)
                    MMA_TF32(acc[mf][nf], a[mf], b[nf]);
        }
        __syncthreads();
    }

    #pragma unroll
    for (int mf = 0; mf < 2; mf++) {
        int r0 = rowBase + wm + mf * 16 + lq;
        #pragma unroll
        for (int half = 0; half < 2; half++) {
            int row = r0 + half * 8;
            if (row >= N) continue;
            #pragma unroll
            for (int nf = 0; nf < 8; nf++) {
                int col = colBase + wn + nf * 8 + lr * 2;
                float v0 = acc[mf][nf][half * 2];
                float v1 = acc[mf][nf][half * 2 + 1];
                if (mode == 0) {
                    *(float2*)&outf[(size_t)row * ncols + col] = make_float2(v0, v1);
                } else {
                    v0 = gelu_f(v0 + bias[col]);
                    v1 = gelu_f(v1 + bias[col + 1]);
                    *(__half2*)&outh[(size_t)row * ncols + col] =
                        __float22half2_rn(make_float2(v0, v1));
                }
            }
        }
    }
}

// ---- GEMM3: fp16 A operand (F1), fp32 W, out = res + gelu(acc+bias) ----
// Same 128x128 tile / 2-stage structure; A smem tile is fp16 (pitch 40 halves).
#define APITCHH 40
#define ABUFH_B (128 * APITCHH * 2)          // bytes per A buffer
#define WOFF_B  (2 * ABUFH_B)                // W buffers start (bytes)
#define GEMM3_SMEM (WOFF_B + 2 * WBUF * (int)sizeof(float))

__global__ void __launch_bounds__(256, 2) k_gemm3(
    const __half* __restrict__ Ah, const float* __restrict__ W,
    const float* __restrict__ bias, const float* __restrict__ res,
    float* __restrict__ out, int N, int K, int ncols)
{
    extern __shared__ float sm[];
    char* smc = (char*)sm;
    uint32_t smb = smem_u32(sm);
    int tid = threadIdx.x, wid = tid >> 5, lane = tid & 31;
    int rowBase = blockIdx.x * 128, colBase = blockIdx.y * 128;
    int wm = (wid & 3) * 32;
    int wn = (wid >> 2) * 64;
    int lq = lane >> 2, lr = lane & 3;

    auto issue = [&](int ch) {
        int kc = ch * KCH;
        int buf = ch & 1;
        uint32_t asb = smb + (uint32_t)(buf * ABUFH_B);
        uint32_t wsb = smb + (uint32_t)WOFF_B + (uint32_t)(buf * WBUF) * 4u;
        #pragma unroll
        for (int i = 0; i < 2; i++) {
            int c = tid + i * 256;            // A: 512 chunks of 16B (8 halves)
            int r = c >> 2, kp = (c & 3) << 3;
            int gr = rowBase + r;
            const __half* src = &Ah[(size_t)gr * K + kc + kp];
            uint32_t dst = asb + (uint32_t)(r * APITCHH + kp) * 2u;
            int sz = (gr < N) ? 16 : 0;
            asm volatile("cp.async.ca.shared.global [%0], [%1], 16, %2;"
                         :: "r"(dst), "l"(src), "r"(sz));
        }
        #pragma unroll
        for (int i = 0; i < 4; i++) {
            int c = tid + i * 256;            // W: 1024 chunks of 16B
            int rr = c >> 5, np = (c & 31) << 2;
            const float* src = &W[(size_t)(kc + rr) * ncols + colBase + np];
            uint32_t dst = wsb + (uint32_t)(rr * WPITCH + np) * 4u;
            asm volatile("cp.async.ca.shared.global [%0], [%1], 16;"
                         :: "r"(dst), "l"(src));
        }
        asm volatile("cp.async.commit_group;");
    };

    float acc[2][8][4];
    #pragma unroll
    for (int i = 0; i < 2; i++)
        #pragma unroll
        for (int j = 0; j < 8; j++)
            #pragma unroll
            for (int k = 0; k < 4; k++) acc[i][j][k] = 0.0f;

    int nch = K / KCH;
    issue(0);
    for (int ch = 0; ch < nch; ch++) {
        if (ch + 1 < nch) {
            issue(ch + 1);
            asm volatile("cp.async.wait_group 1;");
        } else {
            asm volatile("cp.async.wait_group 0;");
        }
        __syncthreads();
        const __half* As = (const __half*)(smc + (ch & 1) * ABUFH_B);
        const float*  Ws = (const float*)(smc + WOFF_B) + (ch & 1) * WBUF;
        #pragma unroll
        for (int ks = 0; ks < KCH; ks += 8) {
            uint32_t a[2][4], b[8][2];
            #pragma unroll
            for (int mf = 0; mf < 2; mf++) {
                int r0 = wm + mf * 16 + lq;
                a[mf][0] = __float_as_uint(__half2float(As[r0 * APITCHH + ks + lr]));
                a[mf][1] = __float_as_uint(__half2float(As[(r0 + 8) * APITCHH + ks + lr]));
                a[mf][2] = __float_as_uint(__half2float(As[r0 * APITCHH + ks + lr + 4]));
                a[mf][3] = __float_as_uint(__half2float(As[(r0 + 8) * APITCHH + ks + lr + 4]));
            }
            #pragma unroll
            for (int nf = 0; nf < 8; nf++) {
                int c0 = wn + nf * 8 + lq;
                b[nf][0] = __float_as_uint(Ws[(ks + lr) * WPITCH + c0]);
                b[nf][1] = __float_as_uint(Ws[(ks + lr + 4) * WPITCH + c0]);
            }
            #pragma unroll
            for (int mf = 0; mf < 2; mf++)
                #pragma unroll
                for (int nf = 0; nf < 8; nf++)
                    MMA_TF32(acc[mf][nf], a[mf], b[nf]);
        }
        __syncthreads();
    }

    #pragma unroll
    for (int mf = 0; mf < 2; mf++) {
        int r0 = rowBase + wm + mf * 16 + lq;
        #pragma unroll
        for (int half = 0; half < 2; half++) {
            int row = r0 + half * 8;
            if (row >= N) continue;
            #pragma unroll
            for (int nf = 0; nf < 8; nf++) {
                int col = colBase + wn + nf * 8 + lr * 2;
                float2 r2 = *(const float2*)&res[(size_t)row * ncols + col];
                float v0 = r2.x + gelu_f(acc[mf][nf][half * 2]     + bias[col]);
                float v1 = r2.y + gelu_f(acc[mf][nf][half * 2 + 1] + bias[col + 1]);
                *(float2*)&out[(size_t)row * ncols + col] = make_float2(v0, v1);
            }
        }
    }
}

// ---------------- launch ----------------
extern "C" void kernel_launch(void* const* d_in, const int* in_sizes, int n_in,
                              void* d_out, int out_size) {
    const float* x    = (const float*)d_in[0];
    const void*  ei   = d_in[1];
    const float* ln1g = (const float*)d_in[3];
    const float* ln1b = (const float*)d_in[4];
    const float* Wc   = (const float*)d_in[5];
    const float* bc   = (const float*)d_in[6];
    const float* ln2g = (const float*)d_in[7];
    const float* ln2b = (const float*)d_in[8];
    const float* W1   = (const float*)d_in[9];
    const float* b1   = (const float*)d_in[10];
    const float* W2   = (const float*)d_in[11];
    const float* b2   = (const float*)d_in[12];
    float* out = (float*)d_out;

    int N = in_sizes[0] / D;
    int E = in_sizes[1] / 2;

    static int inited = 0;
    static cudaStream_t s2;
    static cudaEvent_t evFork, evJoin;
    if (!inited) {
        cudaFuncSetAttribute(k_gemm_tc, cudaFuncAttributeMaxDynamicSharedMemorySize, GEMM_SMEM);
        cudaFuncSetAttribute(k_gemm3, cudaFuncAttributeMaxDynamicSharedMemorySize, GEMM3_SMEM);
        cudaStreamCreateWithFlags(&s2, cudaStreamNonBlocking);
        cudaEventCreateWithFlags(&evFork, cudaEventDisableTiming);
        cudaEventCreateWithFlags(&evJoin, cudaEventDisableTiming);
        inited = 1;
    }

    float*  gH;   cudaGetSymbolAddress((void**)&gH,   g_H);
    float*  gHW;  cudaGetSymbolAddress((void**)&gHW,  g_HW);
    __half* gF1h; cudaGetSymbolAddress((void**)&gF1h, g_F1h);
    float*  gWr;  cudaGetSymbolAddress((void**)&gWr,  g_Wr);

    dim3 lnBlk(32, 8);
    int lnGrid = (N + 7) / 8;
    int rowBlocks = (N + 127) / 128;
    int NB = (N + 1023) / 1024;

    // fork: side stream handles CSR build + W1/W2 prep
    cudaEventRecord(evFork, 0);
    cudaStreamWaitEvent(s2, evFork, 0);

    // 0. (s2) detect + zero degrees
    k_detect_init<<<(N + 255) / 256, 256, 0, s2>>>((const unsigned long long*)ei,
                                                   (long long)E, (unsigned long long)N, N);
    // 1. (main) round Wc
    k_prepwc<<<(D * D + 255) / 256, 256>>>(Wc);
    // 2. (main) H = tf32r(gelu(LN1(x)))
    k_rowln1<<<lnGrid, lnBlk>>>(x, ln1g, ln1b, gH, N);
    // 3. (main) HW = H @ Wc    <-- PROFILED LAUNCH
    k_gemm_tc<<<dim3(rowBlocks, 1), 256, GEMM_SMEM>>>(
        gH, gWr + WR_WC, nullptr, gHW, nullptr, N, D, D, 0);
    // 4-9. (s2) degree histogram -> scan -> fill -> W1/W2 prep
    k_degcount<<<(E + 255) / 256, 256, 0, s2>>>(ei, E);
    k_scan1<<<NB, 1024, 0, s2>>>(N);
    k_scan2<<<1, 128, 0, s2>>>(NB);
    k_scan3<<<(N + 256) / 256, 256, 0, s2>>>(N, E);
    k_fill<<<(E + 255) / 256, 256, 0, s2>>>(ei, E);
    k_prepw12<<<(D * D4 + 255) / 256, 256, 0, s2>>>(W1, W2);
    cudaEventRecord(evJoin, s2);

    // join: gather needs GEMM1 (main) + CSR/dinv (s2)
    cudaStreamWaitEvent(0, evJoin, 0);

    // 10. H = tf32r(LN2(x + agg + b_conv))
    {
        int wpb = 8;
        int blocks = (N + wpb - 1) / wpb;
        k_gather_ln2<<<blocks, wpb * 32>>>(x, bc, ln2g, ln2b, gH, N);
    }
    // 11. F1 = fp16(gelu(H @ W1 + b1))   [fp16 grid == tf32 grid]
    k_gemm_tc<<<dim3(rowBlocks, 4), 256, GEMM_SMEM>>>(
        gH, gWr + WR_W1, b1, nullptr, gF1h, N, D, D4, 1);
    // 12. out = x + gelu(F1 @ W2 + b2)   [fp16 A operand]
    k_gemm3<<<dim3(rowBlocks, 1), 256, GEMM3_SMEM>>>(
        gF1h, gWr + WR_W2, b2, x, out, N, D4, D);
}

// round 17
// speedup vs baseline: 1.4314x; 1.3352x over previous
#include <cuda_runtime.h>
#include <cuda_fp16.h>
#include <math.h>
#include <stdint.h>

#define D    128
#define D4   512
#define MAXN 100000
#define MAXE 1000000

// ---------------- scratch (no allocations allowed) ----------------
__device__ __half g_Hh [MAXN * D];   // gelu(LN1(x)) / LN2(conv), fp16 (11-bit grid)
__device__ float  g_HW [MAXN * D];   // h @ W_conv (raw fp32)
__device__ __half g_F1h[MAXN * D4];  // FFN hidden, fp16
__device__ __half g_Wh [D * D + 2 * D * D4];  // fp16 W transposed: Wc^T | W1^T | W2^T
__device__ int    g_deg [MAXN];
__device__ int    g_scanI[MAXN];
__device__ int    g_bsum[128];
__device__ int    g_off [MAXN + 1];
__device__ int    g_pos [MAXN];
__device__ int    g_csr [MAXE];
__device__ float  g_dinv[MAXN];
__device__ int    g_eflag;           // 1 => edge_index stored as int32

#define WH_WC 0
#define WH_W1 (D * D)
#define WH_W2 (D * D + D * D4)

__device__ __forceinline__ float gelu_f(float x) {
    return 0.5f * x * (1.0f + erff(x * 0.70710678118654752f));
}
__device__ __forceinline__ uint32_t smem_u32(const void* p) {
    uint32_t a;
    asm("{ .reg .u64 t; cvta.to.shared.u64 t, %1; cvt.u32.u64 %0, t; }"
        : "=r"(a) : "l"(p));
    return a;
}
#define MMA_F16(acc, a, b) \
    asm volatile( \
        "mma.sync.aligned.m16n8k16.row.col.f32.f16.f16.f32 " \
        "{%0,%1,%2,%3}, {%4,%5,%6,%7}, {%8,%9}, {%0,%1,%2,%3};" \
        : "+f"((acc)[0]), "+f"((acc)[1]), "+f"((acc)[2]), "+f"((acc)[3]) \
        : "r"((a)[0]), "r"((a)[1]), "r"((a)[2]), "r"((a)[3]), \
          "r"((b)[0]), "r"((b)[1]))

// ------- detect edge dtype + zero degree (side stream) -------
__global__ void k_detect_init(const unsigned long long* __restrict__ p, long long E,
                              unsigned long long NN, int N) {
    int i = blockIdx.x * blockDim.x + threadIdx.x;
    if (i < N) g_deg[i] = 0;
    if (blockIdx.x == 0) {
        __shared__ int bad;
        if (threadIdx.x == 0) bad = 0;
        __syncthreads();
        long long step = E / (long long)blockDim.x;
        if (step < 1) step = 1;
        long long idx = (long long)threadIdx.x * step;
        if (idx < E && p[idx] >= NN) bad = 1;
        __syncthreads();
        if (threadIdx.x == 0) g_eflag = bad;
    }
}

// ------- Wc -> fp16 transposed [n][K] (main stream, before GEMM1) -------
__global__ void k_prepwc(const float* __restrict__ Wc) {
    int i = blockIdx.x * blockDim.x + threadIdx.x;
    if (i < D * D) {
        int k = i / D, n = i % D;
        g_Wh[WH_WC + n * D + k] = __float2half_rn(Wc[i]);
    }
}

// ------- W1,W2 -> fp16 transposed (side stream) -------
__global__ void k_prepw12(const float* __restrict__ W1, const float* __restrict__ W2) {
    int i = blockIdx.x * blockDim.x + threadIdx.x;
    if (i < D * D4) {
        int k1 = i / D4, n1 = i % D4;           // W1: [D][D4]
        g_Wh[WH_W1 + n1 * D + k1] = __float2half_rn(W1[i]);
        int k2 = i / D, n2 = i % D;             // W2: [D4][D]
        g_Wh[WH_W2 + n2 * D4 + k2] = __float2half_rn(W2[i]);
    }
}

// ---------------- LN1 + gelu -> fp16 ----------------
__global__ void k_rowln1(const float* __restrict__ x,
                         const float* __restrict__ g, const float* __restrict__ b,
                         __half* __restrict__ out, int N) {
    int row = blockIdx.x * blockDim.y + threadIdx.y;
    if (row >= N) return;
    int l = threadIdx.x;
    float4 v = ((const float4*)(x + (size_t)row * D))[l];
    float s  = v.x + v.y + v.z + v.w;
    float ss = v.x*v.x + v.y*v.y + v.z*v.z + v.w*v.w;
    #pragma unroll
    for (int o = 16; o; o >>= 1) {
        s  += __shfl_xor_sync(0xffffffffu, s,  o);
        ss += __shfl_xor_sync(0xffffffffu, ss, o);
    }
    float mu  = s * (1.0f / D);
    float var = ss * (1.0f / D) - mu * mu;
    float rs  = rsqrtf(var + 1e-5f);
    float4 gg = ((const float4*)g)[l];
    float4 bb = ((const float4*)b)[l];
    __half2 h0 = __float22half2_rn(make_float2(
        gelu_f((v.x - mu) * rs * gg.x + bb.x),
        gelu_f((v.y - mu) * rs * gg.y + bb.y)));
    __half2 h1 = __float22half2_rn(make_float2(
        gelu_f((v.z - mu) * rs * gg.z + bb.z),
        gelu_f((v.w - mu) * rs * gg.w + bb.w)));
    ((__half2*)(out + (size_t)row * D))[2 * l]     = h0;
    ((__half2*)(out + (size_t)row * D))[2 * l + 1] = h1;
}

// ---------------- degree histogram ----------------
__global__ void k_degcount(const void* __restrict__ ei, int E) {
    int e = blockIdx.x * blockDim.x + threadIdx.x;
    if (e >= E) return;
    int dst;
    if (g_eflag) dst = ((const int*)ei)[E + e];
    else         dst = (int)((const long long*)ei)[E + e];
    atomicAdd(&g_deg[dst], 1);
}

// ---------------- parallel 3-phase scan ----------------
__global__ void k_scan1(int N) {
    __shared__ int sm[1024];
    int i = blockIdx.x * 1024 + threadIdx.x;
    int v = (i < N) ? g_deg[i] : 0;
    sm[threadIdx.x] = v;
    __syncthreads();
    #pragma unroll
    for (int off = 1; off < 1024; off <<= 1) {
        int t = (threadIdx.x >= off) ? sm[threadIdx.x - off] : 0;
        __syncthreads();
        sm[threadIdx.x] += t;
        __syncthreads();
    }
    if (i < N) g_scanI[i] = sm[threadIdx.x];
    if (threadIdx.x == 1023) g_bsum[blockIdx.x] = sm[1023];
}
__global__ void k_scan2(int NB) {
    __shared__ int sm[128];
    int t = threadIdx.x;
    sm[t] = (t < NB) ? g_bsum[t] : 0;
    __syncthreads();
    #pragma unroll
    for (int off = 1; off < 128; off <<= 1) {
        int v = (t >= off) ? sm[t - off] : 0;
        __syncthreads();
        sm[t] += v;
        __syncthreads();
    }
    if (t < NB) g_bsum[t] = sm[t];
}
__global__ void k_scan3(int N, int E) {
    int i = blockIdx.x * blockDim.x + threadIdx.x;
    if (i > N) return;
    if (i == N) { g_off[N] = E; return; }
    int blk = i >> 10;
    int base = blk ? g_bsum[blk - 1] : 0;
    int d = g_deg[i];
    int off = base + g_scanI[i] - d;
    g_off[i] = off;
    g_pos[i] = off;
    g_dinv[i] = rsqrtf((float)(d + 1));
}

// ---------------- CSR fill ----------------
__global__ void k_fill(const void* __restrict__ ei, int E) {
    int e = blockIdx.x * blockDim.x + threadIdx.x;
    if (e >= E) return;
    int s, d2;
    if (g_eflag) { const int* p = (const int*)ei; s = p[e]; d2 = p[E + e]; }
    else { const long long* p = (const long long*)ei; s = (int)p[e]; d2 = (int)p[E + e]; }
    int pos = atomicAdd(&g_pos[d2], 1);
    g_csr[pos] = s;
}

// ------- gather (MLP=4) fused with LN2 -> fp16 -------
__global__ void k_gather_ln2(const float* __restrict__ x,
                             const float* __restrict__ bconv,
                             const float* __restrict__ g, const float* __restrict__ b,
                             __half* __restrict__ out, int N) {
    int row = blockIdx.x * (blockDim.x >> 5) + (threadIdx.x >> 5);
    if (row >= N) return;
    int lane = threadIdx.x & 31;
    float di = g_dinv[row];
    float4 acc = ((const float4*)g_HW)[row * 32 + lane];   // self term
    acc.x *= di; acc.y *= di; acc.z *= di; acc.w *= di;
    int e = g_off[row], e1 = g_off[row + 1];
    for (; e + 4 <= e1; e += 4) {
        int s0 = g_csr[e], s1 = g_csr[e + 1], s2 = g_csr[e + 2], s3 = g_csr[e + 3];
        float c0 = g_dinv[s0], c1 = g_dinv[s1], c2 = g_dinv[s2], c3 = g_dinv[s3];
        float4 v0 = ((const float4*)g_HW)[s0 * 32 + lane];
        float4 v1 = ((const float4*)g_HW)[s1 * 32 + lane];
        float4 v2 = ((const float4*)g_HW)[s2 * 32 + lane];
        float4 v3 = ((const float4*)g_HW)[s3 * 32 + lane];
        acc.x += (v0.x*c0 + v1.x*c1) + (v2.x*c2 + v3.x*c3);
        acc.y += (v0.y*c0 + v1.y*c1) + (v2.y*c2 + v3.y*c3);
        acc.z += (v0.z*c0 + v1.z*c1) + (v2.z*c2 + v3.z*c3);
        acc.w += (v0.w*c0 + v1.w*c1) + (v2.w*c2 + v3.w*c3);
    }
    for (; e < e1; e++) {
        int s = g_csr[e];
        float c = g_dinv[s];
        float4 v = ((const float4*)g_HW)[s * 32 + lane];
        acc.x += v.x*c; acc.y += v.y*c; acc.z += v.z*c; acc.w += v.w*c;
    }
    float4 xv  = ((const float4*)x)[row * 32 + lane];
    float4 bcv = ((const float4*)bconv)[lane];
    float4 v;
    v.x = xv.x + acc.x * di + bcv.x;
    v.y = xv.y + acc.y * di + bcv.y;
    v.z = xv.z + acc.z * di + bcv.z;
    v.w = xv.w + acc.w * di + bcv.w;
    float s  = v.x + v.y + v.z + v.w;
    float ss = v.x*v.x + v.y*v.y + v.z*v.z + v.w*v.w;
    #pragma unroll
    for (int o = 16; o; o >>= 1) {
        s  += __shfl_xor_sync(0xffffffffu, s,  o);
        ss += __shfl_xor_sync(0xffffffffu, ss, o);
    }
    float mu  = s * (1.0f / D);
    float var = ss * (1.0f / D) - mu * mu;
    float rs  = rsqrtf(var + 1e-5f);
    float4 gg = ((const float4*)g)[lane];
    float4 bb = ((const float4*)b)[lane];
    __half2 h0 = __float22half2_rn(make_float2(
        (v.x - mu) * rs * gg.x + bb.x, (v.y - mu) * rs * gg.y + bb.y));
    __half2 h1 = __float22half2_rn(make_float2(
        (v.z - mu) * rs * gg.z + bb.z, (v.w - mu) * rs * gg.w + bb.w));
    ((__half2*)(out + (size_t)row * D))[2 * lane]     = h0;
    ((__half2*)(out + (size_t)row * D))[2 * lane + 1] = h1;
}

// ---- fp16 HMMA GEMM: 128x128 tile, KCH=64, 2-stage cp.async, 2 CTA/SM ----
// A fp16 [row][K]; Wt fp16 transposed [n][K]. Warps 4(m)x2(n), tile 32x64.
// mode 0: raw fp32. 1: fp16(gelu(acc+bias)). 2: res + gelu(acc+bias) fp32.
#define KCH 64
#define AP  72
#define ABUF_B (128 * AP * 2)        // 18432 bytes per buffer
#define WOFF_B (2 * ABUF_B)
#define GEMM_SMEM (4 * ABUF_B)       // 73728

__global__ void __launch_bounds__(256, 2) k_gemm_f16(
    const __half* __restrict__ A, const __half* __restrict__ Wt,
    const float* __restrict__ bias, const float* __restrict__ res,
    float* __restrict__ outf, __half* __restrict__ outh,
    int N, int K, int NC, int mode)
{
    extern __shared__ char smc[];
    uint32_t smb = smem_u32(smc);
    int tid = threadIdx.x, wid = tid >> 5, lane = tid & 31;
    int rowBase = blockIdx.x * 128, colBase = blockIdx.y * 128;
    int wm = (wid & 3) * 32;
    int wn = (wid >> 2) * 64;
    int lq = lane >> 2, lr = lane & 3;

    auto issue = [&](int ch) {
        int kc = ch * KCH;
        int buf = ch & 1;
        uint32_t asb = smb + (uint32_t)(buf * ABUF_B);
        uint32_t wsb = smb + (uint32_t)WOFF_B + (uint32_t)(buf * ABUF_B);
        #pragma unroll
        for (int i = 0; i < 4; i++) {
            int c = tid + i * 256;            // A: 1024 chunks of 16B (8 halves)
            int r = c >> 3, kp = (c & 7) << 3;
            int gr = rowBase + r;
            const __half* src = &A[(size_t)gr * K + kc + kp];
            uint32_t dst = asb + (uint32_t)(r * AP + kp) * 2u;
            int sz = (gr < N) ? 16 : 0;
            asm volatile("cp.async.ca.shared.global [%0], [%1], 16, %2;"
                         :: "r"(dst), "l"(src), "r"(sz));
        }
        #pragma unroll
        for (int i = 0; i < 4; i++) {
            int c = tid + i * 256;            // W: 1024 chunks of 16B
            int r = c >> 3, kp = (c & 7) << 3;
            const __half* src = &Wt[(size_t)(colBase + r) * K + kc + kp];
            uint32_t dst = wsb + (uint32_t)(r * AP + kp) * 2u;
            asm volatile("cp.async.ca.shared.global [%0], [%1], 16;"
                         :: "r"(dst), "l"(src));
        }
        asm volatile("cp.async.commit_group;");
    };

    float acc[2][8][4];
    #pragma unroll
    for (int i = 0; i < 2; i++)
        #pragma unroll
        for (int j = 0; j < 8; j++)
            #pragma unroll
            for (int k = 0; k < 4; k++) acc[i][j][k] = 0.0f;

    int nch = K / KCH;
    issue(0);
    for (int ch = 0; ch < nch; ch++) {
        if (ch + 1 < nch) {
            issue(ch + 1);
            asm volatile("cp.async.wait_group 1;");
        } else {
            asm volatile("cp.async.wait_group 0;");
        }
        __syncthreads();
        const __half* As = (const __half*)(smc + (ch & 1) * ABUF_B);
        const __half* Ws = (const __half*)(smc + WOFF_B + (ch & 1) * ABUF_B);
        #pragma unroll
        for (int ks = 0; ks < KCH; ks += 16) {
            uint32_t a[2][4], b[8][2];
            #pragma unroll
            for (int mf = 0; mf < 2; mf++) {
                int r0 = wm + mf * 16 + lq;
                a[mf][0] = *(const uint32_t*)&As[r0 * AP + ks + 2 * lr];
                a[mf][1] = *(const uint32_t*)&As[(r0 + 8) * AP + ks + 2 * lr];
                a[mf][2] = *(const uint32_t*)&As[r0 * AP + ks + 8 + 2 * lr];
                a[mf][3] = *(const uint32_t*)&As[(r0 + 8) * AP + ks + 8 + 2 * lr];
            }
            #pragma unroll
            for (int nf = 0; nf < 8; nf++) {
                int c0 = wn + nf * 8 + lq;
                b[nf][0] = *(const uint32_t*)&Ws[c0 * AP + ks + 2 * lr];
                b[nf][1] = *(const uint32_t*)&Ws[c0 * AP + ks + 8 + 2 * lr];
            }
            #pragma unroll
            for (int mf = 0; mf < 2; mf++)
                #pragma unroll
                for (int nf = 0; nf < 8; nf++)
                    MMA_F16(acc[mf][nf], a[mf], b[nf]);
        }
        __syncthreads();
    }

    #pragma unroll
    for (int mf = 0; mf < 2; mf++) {
        int r0 = rowBase + wm + mf * 16 + lq;
        #pragma unroll
        for (int half = 0; half < 2; half++) {
            int row = r0 + half * 8;
            if (row >= N) continue;
            #pragma unroll
            for (int nf = 0; nf < 8; nf++) {
                int col = colBase + wn + nf * 8 + lr * 2;
                float v0 = acc[mf][nf][half * 2];
                float v1 = acc[mf][nf][half * 2 + 1];
                if (mode == 0) {
                    *(float2*)&outf[(size_t)row * NC + col] = make_float2(v0, v1);
                } else if (mode == 1) {
                    v0 = gelu_f(v0 + bias[col]);
                    v1 = gelu_f(v1 + bias[col + 1]);
                    *(__half2*)&outh[(size_t)row * NC + col] =
                        __float22half2_rn(make_float2(v0, v1));
                } else {
                    float2 r2 = *(const float2*)&res[(size_t)row * NC + col];
                    v0 = r2.x + gelu_f(v0 + bias[col]);
                    v1 = r2.y + gelu_f(v1 + bias[col + 1]);
                    *(float2*)&outf[(size_t)row * NC + col] = make_float2(v0, v1);
                }
            }
        }
    }
}

// ---------------- launch ----------------
extern "C" void kernel_launch(void* const* d_in, const int* in_sizes, int n_in,
                              void* d_out, int out_size) {
    const float* x    = (const float*)d_in[0];
    const void*  ei   = d_in[1];
    const float* ln1g = (const float*)d_in[3];
    const float* ln1b = (const float*)d_in[4];
    const float* Wc   = (const float*)d_in[5];
    const float* bc   = (const float*)d_in[6];
    const float* ln2g = (const float*)d_in[7];
    const float* ln2b = (const float*)d_in[8];
    const float* W1   = (const float*)d_in[9];
    const float* b1   = (const float*)d_in[10];
    const float* W2   = (const float*)d_in[11];
    const float* b2   = (const float*)d_in[12];
    float* out = (float*)d_out;

    int N = in_sizes[0] / D;
    int E = in_sizes[1] / 2;

    static int inited = 0;
    static cudaStream_t s2;
    static cudaEvent_t evFork, evJoin;
    if (!inited) {
        cudaFuncSetAttribute(k_gemm_f16, cudaFuncAttributeMaxDynamicSharedMemorySize, GEMM_SMEM);
        cudaStreamCreateWithFlags(&s2, cudaStreamNonBlocking);
        cudaEventCreateWithFlags(&evFork, cudaEventDisableTiming);
        cudaEventCreateWithFlags(&evJoin, cudaEventDisableTiming);
        inited = 1;
    }

    __half* gHh;  cudaGetSymbolAddress((void**)&gHh,  g_Hh);
    float*  gHW;  cudaGetSymbolAddress((void**)&gHW,  g_HW);
    __half* gF1h; cudaGetSymbolAddress((void**)&gF1h, g_F1h);
    __half* gWh;  cudaGetSymbolAddress((void**)&gWh,  g_Wh);

    dim3 lnBlk(32, 8);
    int lnGrid = (N + 7) / 8;
    int rowBlocks = (N + 127) / 128;
    int NB = (N + 1023) / 1024;

    // fork: side stream handles CSR build + W1/W2 prep
    cudaEventRecord(evFork, 0);
    cudaStreamWaitEvent(s2, evFork, 0);

    // 0. (s2) detect + zero degrees
    k_detect_init<<<(N + 255) / 256, 256, 0, s2>>>((const unsigned long long*)ei,
                                                   (long long)E, (unsigned long long)N, N);
    // 1. (main) Wc -> fp16 transposed
    k_prepwc<<<(D * D + 255) / 256, 256>>>(Wc);
    // 2. (main) H = fp16(gelu(LN1(x)))
    k_rowln1<<<lnGrid, lnBlk>>>(x, ln1g, ln1b, gHh, N);
    // 3. (main) HW = H @ Wc    <-- PROFILED LAUNCH
    k_gemm_f16<<<dim3(rowBlocks, 1), 256, GEMM_SMEM>>>(
        gHh, gWh + WH_WC, nullptr, nullptr, gHW, nullptr, N, D, D, 0);
    // 4-9. (s2) degree histogram -> scan -> fill -> W1/W2 prep
    k_degcount<<<(E + 255) / 256, 256, 0, s2>>>(ei, E);
    k_scan1<<<NB, 1024, 0, s2>>>(N);
    k_scan2<<<1, 128, 0, s2>>>(NB);
    k_scan3<<<(N + 256) / 256, 256, 0, s2>>>(N, E);
    k_fill<<<(E + 255) / 256, 256, 0, s2>>>(ei, E);
    k_prepw12<<<(D * D4 + 255) / 256, 256, 0, s2>>>(W1, W2);
    cudaEventRecord(evJoin, s2);

    // join: gather needs GEMM1 (main) + CSR/dinv (s2)
    cudaStreamWaitEvent(0, evJoin, 0);

    // 10. H = fp16(LN2(x + agg + b_conv))
    {
        int wpb = 8;
        int blocks = (N + wpb - 1) / wpb;
        k_gather_ln2<<<blocks, wpb * 32>>>(x, bc, ln2g, ln2b, gHh, N);
    }
    // 11. F1 = fp16(gelu(H @ W1 + b1))
    k_gemm_f16<<<dim3(rowBlocks, 4), 256, GEMM_SMEM>>>(
        gHh, gWh + WH_W1, b1, nullptr, nullptr, gF1h, N, D, D4, 1);
    // 12. out = x + gelu(F1 @ W2 + b2)
    k_gemm_f16<<<dim3(rowBlocks, 1), 256, GEMM_SMEM>>>(
        gF1h, gWh + WH_W2, b2, x, out, nullptr, N, D4, D, 2);
}